// round 16
// baseline (speedup 1.0000x reference)
#include <cuda_runtime.h>
#include <cuda_fp16.h>
#include <math.h>

#define T_STEPS 512
#define BATCH   64
#define IDIM    1024
#define HDIM    1024
#define G4      4096
#define MTOT    (T_STEPS * BATCH)

__device__ unsigned g_ctr;
__device__ __half g_xf[(size_t)MTOT * IDIM];      // x fp16, [t*64+b][k]
__device__ __half g_hf[2 * 64 * 1024];            // h fp16, double buffer

__device__ __forceinline__ unsigned smem_u32(const void* p) {
    return (unsigned)__cvta_generic_to_shared(p);
}

#define LDM4(R0, R1, R2, R3, ADDR)                                           \
    asm volatile("ldmatrix.sync.aligned.m8n8.x4.shared.b16 {%0,%1,%2,%3},[%4];" \
                 : "=r"(R0), "=r"(R1), "=r"(R2), "=r"(R3) : "r"(ADDR))
#define MMA_F16(D, A0, A1, A2, A3, B0, B1)                                   \
    asm volatile("mma.sync.aligned.m16n8k16.row.col.f32.f16.f16.f32 "        \
                 "{%0,%1,%2,%3},{%4,%5,%6,%7},{%8,%9},{%0,%1,%2,%3};"        \
                 : "+f"(D[0]), "+f"(D[1]), "+f"(D[2]), "+f"(D[3])            \
                 : "r"(A0), "r"(A1), "r"(A2), "r"(A3), "r"(B0), "r"(B1))

__device__ __forceinline__ void cp16(unsigned dst, const void* src) {
    asm volatile("cp.async.ca.shared.global [%0], [%1], 16;" :: "r"(dst), "l"(src));
}
__device__ __forceinline__ float sigf(float x) { return 1.f / (1.f + expf(-x)); }

// =====================================================================
// conv: input fp32 -> g_xf fp16 (linear layout, 8 elems/thread)
// =====================================================================
__global__ void __launch_bounds__(256) conv_kernel(const float* __restrict__ X)
{
    const size_t gid = (size_t)blockIdx.x * 256 + threadIdx.x;   // < 4194304
    const size_t idx = gid * 8;
    float4 a = *(const float4*)(X + idx);
    float4 b = *(const float4*)(X + idx + 4);
    union { __half h[8]; uint4 v; } H;
    H.h[0] = __float2half_rn(a.x); H.h[1] = __float2half_rn(a.y);
    H.h[2] = __float2half_rn(a.z); H.h[3] = __float2half_rn(a.w);
    H.h[4] = __float2half_rn(b.x); H.h[5] = __float2half_rn(b.y);
    H.h[6] = __float2half_rn(b.z); H.h[7] = __float2half_rn(b.w);
    *(uint4*)(g_xf + idx) = H.v;
}

// =====================================================================
// init: reset barrier + convert h0 -> g_hf buf 0 (fp16)
// =====================================================================
__global__ void init_kernel(const float* __restrict__ h0) {
    if (blockIdx.x == 0 && threadIdx.x == 0) g_ctr = 0u;
    const int idx = blockIdx.x * 256 + threadIdx.x;
    const int b = idx >> 10, j = idx & 1023;
    g_hf[(size_t)b * 1024 + j] = __float2half_rn(h0[(size_t)b * HDIM + j]);
}

// =====================================================================
// Fused persistent kernel: gates = [W_ih | W_hh] . [x_t ; h_t]
// 128 CTAs x 256 thr. 16 chunks/step (8 x + 8 h), single-product fp16.
// Barrier wait deferred until just before first h-chunk issue.
// smem: Wih 66048 | Whh 66048 | 3x17408 stages | Gs 8448 | Cs 2048
//       | Rs 32 | Bs 128
// =====================================================================
#define GC 128
#define WST    1032
#define WIH_O  0
#define WHH_O  66048
#define HT_O   132096
#define HSTG   17408
#define GS_O   (HT_O + 3 * HSTG)     // 184320
#define CS_O   (GS_O + 8448)         // 192768
#define RS_O   (CS_O + 2048)         // 194816
#define BS_O   (RS_O + 32)           // 194848
#define RSMEM  (BS_O + 128)          // 194976
#define GPAD   66

__global__ void __launch_bounds__(256, 1) fused_kernel(
    const float* __restrict__ h0raw, const float* __restrict__ c0,
    const float* __restrict__ wih, const float* __restrict__ whh,
    const float* __restrict__ bih, const float* __restrict__ bhh,
    const float* __restrict__ retr, float* __restrict__ out)
{
    extern __shared__ char s[];
    const unsigned sb = smem_u32(s);
    float* Gs = (float*)(s + GS_O);
    float* Cs = (float*)(s + CS_O);
    float* Rs = (float*)(s + RS_O);
    float* Bs = (float*)(s + BS_O);

    const int tid = threadIdx.x, lane = tid & 31, wid = tid >> 5;
    const int j0 = blockIdx.x * 8;

    // stage W_ih and W_hh slices as fp16 planes
    for (int idx = tid; idx < 32 * 256; idx += 256) {
        const int r = idx >> 8, kq = (idx & 255) << 2;
        const int g = r >> 3, u = r & 7;
        const size_t grow = (size_t)(g * HDIM + j0 + u) * HDIM + kq;
        const float4 vi = *(const float4*)(wih + grow);
        const float4 vh = *(const float4*)(whh + grow);
        __half hi[4], hh[4];
        hi[0] = __float2half_rn(vi.x); hi[1] = __float2half_rn(vi.y);
        hi[2] = __float2half_rn(vi.z); hi[3] = __float2half_rn(vi.w);
        hh[0] = __float2half_rn(vh.x); hh[1] = __float2half_rn(vh.y);
        hh[2] = __float2half_rn(vh.z); hh[3] = __float2half_rn(vh.w);
        *(uint2*)(s + WIH_O + (r * WST + kq) * 2) = *(uint2*)hi;
        *(uint2*)(s + WHH_O + (r * WST + kq) * 2) = *(uint2*)hh;
    }
    if (tid < 8) Rs[tid] = retr[j0 + tid];
    if (tid < 32) {
        const int g = tid >> 3, u = tid & 7;
        const int n = g * HDIM + j0 + u;
        Bs[tid] = bih[n] + bhh[n];
    }
    for (int idx = tid; idx < 512; idx += 256) {
        const int u = idx & 7, b = idx >> 3;
        Cs[u * 64 + b] = c0[(size_t)b * HDIM + j0 + u];
    }
    __syncthreads();

    const int mtile = wid & 1;
    const int npair = wid >> 1;
    const unsigned offA =
        (unsigned)(((mtile * 16 + (lane & 15)) * WST + ((lane >> 4) << 3)) * 2);
    const unsigned offB =
        (unsigned)((npair * 16 + (lane & 7) + ((lane >> 4) << 3)) * 272 +
                   ((((lane >> 3) & 1) << 3) * 2));

    const int u0 = tid & 7,          b0 = tid >> 3;
    const int u1 = (tid + 256) & 7,  b1 = (tid + 256) >> 3;

    float* hT_out = out + (size_t)T_STEPS * BATCH * HDIM;
    float* cT_out = hT_out + (size_t)BATCH * HDIM;

    float hpr[2];
    hpr[0] = __ldg(h0raw + (size_t)b0 * HDIM + j0 + u0);
    hpr[1] = __ldg(h0raw + (size_t)b1 * HDIM + j0 + u1);

    for (int t = 0; t < T_STEPS; ++t) {
        const char* xsrc = (const char*)g_xf + (size_t)t * 131072;
        const char* hsrc = (const char*)g_hf + (size_t)(t & 1) * 131072;

        // chunk C: 0-7 -> x (k = C*128), 8-15 -> h (k = (C-8)*128)
#define ISSUER(C)                                                            \
        {   const char* src = ((C) < 8) ? (xsrc + (C) * 256)                 \
                                        : (hsrc + ((C) - 8) * 256);          \
            const unsigned dstb = sb + HT_O + ((C) % 3) * HSTG;              \
            _Pragma("unroll")                                                \
            for (int i = 0; i < 4; ++i) {                                    \
                const int u = tid + i * 256;                                 \
                const int row = u >> 4, cg = u & 15;                         \
                cp16(dstb + row * 272 + cg * 16,                             \
                     src + (size_t)row * 2048 + cg * 16);                    \
            }                                                                \
            asm volatile("cp.async.commit_group;" ::: "memory");             \
        }

        ISSUER(0); ISSUER(1);

        float acc0[4] = {0.f, 0.f, 0.f, 0.f};
        float acc1[4] = {0.f, 0.f, 0.f, 0.f};

        for (int c = 0; c < 16; ++c) {
            if (c < 15)
                asm volatile("cp.async.wait_group 1;" ::: "memory");
            else
                asm volatile("cp.async.wait_group 0;" ::: "memory");
            // before first h-chunk issue (c+2==8): ensure all CTAs wrote h_t
            if (c == 6 && tid == 0) {
                const unsigned target = (unsigned)t * GC;
                while (*(volatile unsigned*)&g_ctr < target) { }
            }
            __syncthreads();
            if (c + 2 < 16) ISSUER(c + 2);

            const unsigned aplane = sb + ((c < 8) ? WIH_O : WHH_O);
            const unsigned stb = sb + HT_O + (c % 3) * HSTG;
            const int kbase = (c & 7) * 128;
#pragma unroll
            for (int ks = 0; ks < 8; ++ks) {
                const unsigned ka = (unsigned)((kbase + ks * 16) * 2);
                unsigned a0, a1, a2, a3, bh0, bh1, bh2, bh3;
                LDM4(a0, a1, a2, a3, aplane + offA + ka);
                LDM4(bh0, bh1, bh2, bh3, stb + offB + ks * 32);
                MMA_F16(acc0, a0, a1, a2, a3, bh0, bh1);
                MMA_F16(acc1, a0, a1, a2, a3, bh2, bh3);
            }
        }
#undef ISSUER

        {
            const int row = mtile * 16 + (lane >> 2);
            const int col = npair * 16 + (lane & 3) * 2;
            Gs[row * GPAD + col]           = acc0[0];
            Gs[row * GPAD + col + 1]       = acc0[1];
            Gs[(row + 8) * GPAD + col]     = acc0[2];
            Gs[(row + 8) * GPAD + col + 1] = acc0[3];
            Gs[row * GPAD + col + 8]       = acc1[0];
            Gs[row * GPAD + col + 9]       = acc1[1];
            Gs[(row + 8) * GPAD + col + 8] = acc1[2];
            Gs[(row + 8) * GPAD + col + 9] = acc1[3];
        }
        __syncthreads();

        float* o_t = out + (size_t)t * BATCH * HDIM;
        __half* hw = g_hf + (size_t)((t + 1) & 1) * 65536;
        float hy0, hy1;
#pragma unroll
        for (int c2 = 0; c2 < 2; ++c2) {
            const int u = c2 ? u1 : u0, b = c2 ? b1 : b0;
            const int j = j0 + u;

            const float gi = Gs[(0 * 8 + u) * GPAD + b] + Bs[0 * 8 + u];
            const float gf = Gs[(1 * 8 + u) * GPAD + b] + Bs[1 * 8 + u];
            const float gg = Gs[(2 * 8 + u) * GPAD + b] + Bs[2 * 8 + u];
            const float go = Gs[(3 * 8 + u) * GPAD + b] + Bs[3 * 8 + u];

            const float c = Cs[u * 64 + b];
            const float cy = sigf(gf) * c + sigf(gi) * tanhf(gg);
            float hy = sigf(go) * tanhf(cy);
            const float rv = Rs[u];
            hy = rv * hpr[c2] + (1.f - rv) * hy;

            Cs[u * 64 + b] = cy;
            o_t[(size_t)b * HDIM + j] = hy;
            hw[(size_t)b * 1024 + j] = __float2half_rn(hy);
            if (c2) hy1 = hy; else hy0 = hy;
            if (t == T_STEPS - 1) {
                hT_out[(size_t)b * HDIM + j] = hy;
                cT_out[(size_t)b * HDIM + j] = cy;
            }
        }
        hpr[0] = hy0;
        hpr[1] = hy1;

        // arrive only; next iteration's x-phase overlaps the drain
        __threadfence();
        __syncthreads();
        if (tid == 0) atomicAdd(&g_ctr, 1u);
    }
}

// =====================================================================
extern "C" void kernel_launch(void* const* d_in, const int* in_sizes, int n_in,
                              void* d_out, int out_size)
{
    const float* input_ = (const float*)d_in[0];
    const float* h0     = (const float*)d_in[1];
    const float* c0     = (const float*)d_in[2];
    const float* wih    = (const float*)d_in[3];
    const float* whh    = (const float*)d_in[4];
    const float* bih    = (const float*)d_in[5];
    const float* bhh    = (const float*)d_in[6];
    const float* retr   = (const float*)d_in[7];
    float* out = (float*)d_out;
    (void)in_sizes; (void)n_in; (void)out_size;

    cudaFuncSetAttribute(fused_kernel,
                         cudaFuncAttributeMaxDynamicSharedMemorySize, RSMEM);

    conv_kernel<<<16384, 256>>>(input_);
    init_kernel<<<256, 256>>>(h0);
    fused_kernel<<<GC, 256, RSMEM>>>(h0, c0, wih, whh, bih, bhh, retr, out);
}

// round 17
// speedup vs baseline: 1.4289x; 1.4289x over previous
#include <cuda_runtime.h>
#include <cuda_fp16.h>
#include <math.h>

#define T_STEPS 512
#define BATCH   64
#define IDIM    1024
#define HDIM    1024
#define G4      4096
#define MTOT    (T_STEPS * BATCH)

__device__ float g_xg[(size_t)G4 * MTOT];
__device__ unsigned g_ctr;
__device__ char g_wp[(size_t)32 * 32 * 10240];    // W_ih: hi fp16 tiles
__device__ char g_xp[(size_t)256 * 32 * 10240];   // X: hi fp16 tiles
__device__ __half g_hf[2 * 64 * 1024];            // h fp16, double buffer

__device__ __forceinline__ unsigned smem_u32(const void* p) {
    return (unsigned)__cvta_generic_to_shared(p);
}

#define LDM4(R0, R1, R2, R3, ADDR)                                           \
    asm volatile("ldmatrix.sync.aligned.m8n8.x4.shared.b16 {%0,%1,%2,%3},[%4];" \
                 : "=r"(R0), "=r"(R1), "=r"(R2), "=r"(R3) : "r"(ADDR))
#define MMA_F16(D, A0, A1, A2, A3, B0, B1)                                   \
    asm volatile("mma.sync.aligned.m16n8k16.row.col.f32.f16.f16.f32 "        \
                 "{%0,%1,%2,%3},{%4,%5,%6,%7},{%8,%9},{%0,%1,%2,%3};"        \
                 : "+f"(D[0]), "+f"(D[1]), "+f"(D[2]), "+f"(D[3])            \
                 : "r"(A0), "r"(A1), "r"(A2), "r"(A3), "r"(B0), "r"(B1))

__device__ __forceinline__ void cp16(unsigned dst, const void* src) {
    asm volatile("cp.async.ca.shared.global [%0], [%1], 16;" :: "r"(dst), "l"(src));
}
__device__ __forceinline__ float sigf(float x) { return 1.f / (1.f + expf(-x)); }

// =====================================================================
// prep: W -> fp16 hi plane, X -> fp16 hi plane, tile layout
// =====================================================================
__global__ void __launch_bounds__(256) conv_kernel(
    const float* __restrict__ W, const float* __restrict__ X)
{
    const size_t gid = (size_t)blockIdx.x * 256 + threadIdx.x;
    const float* srcbase;
    char* dst;
    unsigned o;
    if (gid < 655360) {
        const size_t pair = gid / 640;
        dst = g_wp + pair * 10240;
        srcbase = W + (pair >> 5) * 128 * 1024 + (pair & 31) * 32;
        o = (unsigned)(gid % 640) * 16;
    } else {
        const size_t pos = gid - 655360;
        const size_t pair = pos / 640;
        dst = g_xp + pair * 10240;
        srcbase = X + (pair >> 5) * 128 * 1024 + (pair & 31) * 32;
        o = (unsigned)(pos % 640) * 16;
    }
    const unsigned row = o / 80, col = (o % 80) >> 1;
    union { __half h[8]; uint4 v; } H;
    if (col >= 32) H.v = make_uint4(0, 0, 0, 0);
    else {
        const float* s = srcbase + (size_t)row * 1024 + col;
        float4 a = *(const float4*)s, b = *(const float4*)(s + 4);
        float f[8] = {a.x, a.y, a.z, a.w, b.x, b.y, b.z, b.w};
#pragma unroll
        for (int j = 0; j < 8; ++j) H.h[j] = __float2half_rn(f[j]);
    }
    *(uint4*)(dst + o) = H.v;
}

// =====================================================================
// Kernel 1: x_gates GEMM, single-product fp16, 3 stages, 3 CTAs/SM
// =====================================================================
#define XSP   40
#define XSTG  20480
#define XSMEM (3 * XSTG)

__global__ void __launch_bounds__(128, 3) xgates_mma_kernel(
    const float* __restrict__ bih, const float* __restrict__ bhh)
{
    extern __shared__ char xsm[];
    const unsigned sb = smem_u32(xsm);
    const int tid = threadIdx.x, lane = tid & 31, wid = tid >> 5;
    const size_t nt = blockIdx.y, mt = blockIdx.x;
    const int n0 = (int)nt * 128, m0 = (int)mt * 128;
    const int wn = (wid & 1) * 64, wm = (wid >> 1) * 64;

    float acc[4][8][4];
#pragma unroll
    for (int f = 0; f < 4; ++f)
#pragma unroll
        for (int q = 0; q < 8; ++q)
#pragma unroll
            for (int r = 0; r < 4; ++r) acc[f][q][r] = 0.f;

    unsigned offA[4], offB[4];
    {
        const int ar = wn + (lane & 15), ac = (lane >> 4) << 3;
#pragma unroll
        for (int f = 0; f < 4; ++f) offA[f] = (unsigned)(((ar + f * 16) * XSP + ac) * 2);
        const int br = wm + (lane & 7) + ((lane >> 4) << 3);
        const int bc = ((lane >> 3) & 1) << 3;
#pragma unroll
        for (int Q = 0; Q < 4; ++Q) offB[Q] = (unsigned)(((br + Q * 16) * XSP + bc) * 2);
    }

    const char* wbase = g_wp + nt * 32 * 10240;
    const char* xbase = g_xp + mt * 32 * 10240;

#define ISSUEX(C)                                                             \
    {   const char* ws = wbase + (size_t)(C) * 10240;                         \
        const char* xs = xbase + (size_t)(C) * 10240;                         \
        unsigned d = sb + ((C) % 3) * XSTG;                                   \
        _Pragma("unroll")                                                     \
        for (int i = 0; i < 5; ++i) {                                         \
            unsigned u = (unsigned)(tid + i * 128) * 16;                      \
            cp16(d + u, ws + u);                                              \
            cp16(d + 10240 + u, xs + u);                                      \
        }                                                                     \
        asm volatile("cp.async.commit_group;" ::: "memory");                  \
    }

#define COMPUTEX(BUF)                                                         \
    {   unsigned base = sb + (BUF) * XSTG;                                    \
        _Pragma("unroll")                                                     \
        for (int kk = 0; kk < 32; kk += 16) {                                 \
            unsigned kb = kk * 2;                                             \
            unsigned bh[8][2];                                                \
            _Pragma("unroll")                                                 \
            for (int Q = 0; Q < 4; ++Q) {                                     \
                unsigned r0, r1, r2, r3;                                      \
                LDM4(r0, r1, r2, r3, base + 10240 + offB[Q] + kb);            \
                bh[Q*2][0] = r0; bh[Q*2][1] = r1;                             \
                bh[Q*2+1][0] = r2; bh[Q*2+1][1] = r3;                         \
            }                                                                 \
            _Pragma("unroll")                                                 \
            for (int f = 0; f < 4; ++f) {                                     \
                unsigned a0, a1, a2, a3;                                      \
                LDM4(a0, a1, a2, a3, base + offA[f] + kb);                    \
                _Pragma("unroll")                                             \
                for (int q = 0; q < 8; ++q)                                   \
                    MMA_F16(acc[f][q], a0, a1, a2, a3, bh[q][0], bh[q][1]);   \
            } } }

    ISSUEX(0); ISSUEX(1);
    for (int c = 0; c < 32; ++c) {
        if (c < 31)
            asm volatile("cp.async.wait_group 1;" ::: "memory");
        else
            asm volatile("cp.async.wait_group 0;" ::: "memory");
        __syncthreads();
        if (c + 2 < 32) ISSUEX(c + 2);
        COMPUTEX(c % 3);
    }
#undef ISSUEX
#undef COMPUTEX

    __syncthreads();
    const int erow = lane >> 2, ecol = (lane & 3) * 2;
#pragma unroll
    for (int f = 0; f < 4; ++f) {
        const int n = n0 + wn + f * 16 + erow;
        const float b0 = bih[n] + bhh[n];
        const float b8 = bih[n + 8] + bhh[n + 8];
#pragma unroll
        for (int q = 0; q < 8; ++q) {
            const int m = m0 + wm + q * 8 + ecol;
            *(float2*)(g_xg + (size_t)n * MTOT + m) =
                make_float2(acc[f][q][0] + b0, acc[f][q][1] + b0);
            *(float2*)(g_xg + (size_t)(n + 8) * MTOT + m) =
                make_float2(acc[f][q][2] + b8, acc[f][q][3] + b8);
        }
    }
}

// =====================================================================
// init: reset barrier + convert h0 -> g_hf buf 0 (fp16)
// =====================================================================
__global__ void init_kernel(const float* __restrict__ h0) {
    if (blockIdx.x == 0 && threadIdx.x == 0) g_ctr = 0u;
    const int idx = blockIdx.x * 256 + threadIdx.x;
    const int b = idx >> 10, j = idx & 1023;
    g_hf[(size_t)b * 1024 + j] = __float2half_rn(h0[(size_t)b * HDIM + j]);
}

// =====================================================================
// Kernel 2: recurrent. Single-product fp16, KC=256 (4 chunks), 3 stages,
// split grid barrier. smem: Whi 66048 | 3x33792 | Gs 8448 | Cs 2048 | Rs 32
// =====================================================================
#define GC 128
#define WST    1032
#define WHI_O  0
#define HT_O   66048
#define HSTG   33792                 // 64 rows x 528 B
#define GS_O   (HT_O + 3 * HSTG)     // 167424
#define CS_O   (GS_O + 8448)
#define RS_O   (CS_O + 2048)
#define RSMEM  (RS_O + 32)
#define GPAD   66

__global__ void __launch_bounds__(256, 1) recurrent_kernel(
    const float* __restrict__ h0raw, const float* __restrict__ c0,
    const float* __restrict__ whh, const float* __restrict__ retr,
    float* __restrict__ out)
{
    extern __shared__ char s[];
    const unsigned sb = smem_u32(s);
    float* Gs = (float*)(s + GS_O);
    float* Cs = (float*)(s + CS_O);
    float* Rs = (float*)(s + RS_O);

    const int tid = threadIdx.x, lane = tid & 31, wid = tid >> 5;
    const int j0 = blockIdx.x * 8;

    for (int idx = tid; idx < 32 * 256; idx += 256) {
        const int r = idx >> 8, kq = (idx & 255) << 2;
        const int g = r >> 3, u = r & 7;
        const float4 v = *(const float4*)(whh + (size_t)(g * HDIM + j0 + u) * HDIM + kq);
        __half hi[4];
        hi[0] = __float2half_rn(v.x); hi[1] = __float2half_rn(v.y);
        hi[2] = __float2half_rn(v.z); hi[3] = __float2half_rn(v.w);
        *(uint2*)(s + WHI_O + (r * WST + kq) * 2) = *(uint2*)hi;
    }
    if (tid < 8) Rs[tid] = retr[j0 + tid];
    for (int idx = tid; idx < 512; idx += 256) {
        const int u = idx & 7, b = idx >> 3;
        Cs[u * 64 + b] = c0[(size_t)b * HDIM + j0 + u];
    }
    __syncthreads();

    const int mtile = wid & 1;
    const int npair = wid >> 1;
    const unsigned offA =
        (unsigned)(((mtile * 16 + (lane & 15)) * WST + ((lane >> 4) << 3)) * 2);
    const unsigned offB =
        (unsigned)((npair * 16 + (lane & 7) + ((lane >> 4) << 3)) * 528 +
                   ((((lane >> 3) & 1) << 3) * 2));

    const int u0 = tid & 7,          b0 = tid >> 3;
    const int u1 = (tid + 256) & 7,  b1 = (tid + 256) >> 3;

    float* hT_out = out + (size_t)T_STEPS * BATCH * HDIM;
    float* cT_out = hT_out + (size_t)BATCH * HDIM;

    float xgr[8], hpr[2];
#pragma unroll
    for (int g = 0; g < 4; ++g) {
        xgr[g]     = __ldg(g_xg + (size_t)(g * HDIM + j0 + u0) * MTOT + b0);
        xgr[4 + g] = __ldg(g_xg + (size_t)(g * HDIM + j0 + u1) * MTOT + b1);
    }
    hpr[0] = __ldg(h0raw + (size_t)b0 * HDIM + j0 + u0);
    hpr[1] = __ldg(h0raw + (size_t)b1 * HDIM + j0 + u1);

    for (int t = 0; t < T_STEPS; ++t) {
        const char* hsrc = (const char*)g_hf + (size_t)(t & 1) * 131072;

        // chunk: 64 rows x 256 k fp16 = 32KB -> 2048 x 16B, 8/thread
#define ISSUER(C)                                                            \
        {   const unsigned dstb = sb + HT_O + ((C) % 3) * HSTG;              \
            _Pragma("unroll")                                                \
            for (int i = 0; i < 8; ++i) {                                    \
                const int u = tid + i * 256;                                 \
                const int row = u >> 5, cg = u & 31;                         \
                cp16(dstb + row * 528 + cg * 16,                             \
                     hsrc + (size_t)row * 2048 + (C) * 512 + cg * 16);       \
            }                                                                \
            asm volatile("cp.async.commit_group;" ::: "memory");             \
        }

        ISSUER(0); ISSUER(1);

        float acc0[4] = {0.f, 0.f, 0.f, 0.f};
        float acc1[4] = {0.f, 0.f, 0.f, 0.f};

        for (int c = 0; c < 4; ++c) {
            if (c < 3)
                asm volatile("cp.async.wait_group 1;" ::: "memory");
            else
                asm volatile("cp.async.wait_group 0;" ::: "memory");
            __syncthreads();
            if (c + 2 < 4) ISSUER(c + 2);

            const unsigned stb = sb + HT_O + (c % 3) * HSTG;
#pragma unroll
            for (int ks = 0; ks < 16; ++ks) {
                const unsigned ka = (unsigned)((c * 256 + ks * 16) * 2);
                unsigned ah0, ah1, ah2, ah3;
                unsigned bh0, bh1, bh2, bh3;
                LDM4(ah0, ah1, ah2, ah3, sb + WHI_O + offA + ka);
                LDM4(bh0, bh1, bh2, bh3, stb + offB + ks * 32);
                MMA_F16(acc0, ah0, ah1, ah2, ah3, bh0, bh1);
                MMA_F16(acc1, ah0, ah1, ah2, ah3, bh2, bh3);
            }
        }
#undef ISSUER

        {
            const int row = mtile * 16 + (lane >> 2);
            const int col = npair * 16 + (lane & 3) * 2;
            Gs[row * GPAD + col]           = acc0[0];
            Gs[row * GPAD + col + 1]       = acc0[1];
            Gs[(row + 8) * GPAD + col]     = acc0[2];
            Gs[(row + 8) * GPAD + col + 1] = acc0[3];
            Gs[row * GPAD + col + 8]       = acc1[0];
            Gs[row * GPAD + col + 9]       = acc1[1];
            Gs[(row + 8) * GPAD + col + 8] = acc1[2];
            Gs[(row + 8) * GPAD + col + 9] = acc1[3];
        }
        __syncthreads();

        float* o_t = out + (size_t)t * BATCH * HDIM;
        __half* hw = g_hf + (size_t)((t + 1) & 1) * 65536;
        float hy0, hy1;
#pragma unroll
        for (int c2 = 0; c2 < 2; ++c2) {
            const int u = c2 ? u1 : u0, b = c2 ? b1 : b0;
            const int j = j0 + u;

            const float gi = Gs[(0 * 8 + u) * GPAD + b] + xgr[c2 * 4 + 0];
            const float gf = Gs[(1 * 8 + u) * GPAD + b] + xgr[c2 * 4 + 1];
            const float gg = Gs[(2 * 8 + u) * GPAD + b] + xgr[c2 * 4 + 2];
            const float go = Gs[(3 * 8 + u) * GPAD + b] + xgr[c2 * 4 + 3];

            const float c = Cs[u * 64 + b];
            const float cy = sigf(gf) * c + sigf(gi) * tanhf(gg);
            float hy = sigf(go) * tanhf(cy);
            const float rv = Rs[u];
            hy = rv * hpr[c2] + (1.f - rv) * hy;

            Cs[u * 64 + b] = cy;
            o_t[(size_t)b * HDIM + j] = hy;
            hw[(size_t)b * 1024 + j] = __float2half_rn(hy);
            if (c2) hy1 = hy; else hy0 = hy;
            if (t == T_STEPS - 1) {
                hT_out[(size_t)b * HDIM + j] = hy;
                cT_out[(size_t)b * HDIM + j] = cy;
            }
        }

        __threadfence();
        __syncthreads();
        if (tid == 0) atomicAdd(&g_ctr, 1u);

        if (t + 1 < T_STEPS) {
            const size_t m0n = (size_t)(t + 1) * BATCH + b0;
            const size_t m1n = (size_t)(t + 1) * BATCH + b1;
#pragma unroll
            for (int g = 0; g < 4; ++g) {
                xgr[g]     = __ldg(g_xg + (size_t)(g * HDIM + j0 + u0) * MTOT + m0n);
                xgr[4 + g] = __ldg(g_xg + (size_t)(g * HDIM + j0 + u1) * MTOT + m1n);
            }
            hpr[0] = hy0;
            hpr[1] = hy1;
        }

        if (tid == 0) {
            const unsigned target = (unsigned)(t + 1) * GC;
            while (*(volatile unsigned*)&g_ctr < target) { }
        }
        __syncthreads();
    }
}

// =====================================================================
extern "C" void kernel_launch(void* const* d_in, const int* in_sizes, int n_in,
                              void* d_out, int out_size)
{
    const float* input_ = (const float*)d_in[0];
    const float* h0     = (const float*)d_in[1];
    const float* c0     = (const float*)d_in[2];
    const float* wih    = (const float*)d_in[3];
    const float* whh    = (const float*)d_in[4];
    const float* bih    = (const float*)d_in[5];
    const float* bhh    = (const float*)d_in[6];
    const float* retr   = (const float*)d_in[7];
    float* out = (float*)d_out;
    (void)in_sizes; (void)n_in; (void)out_size;

    cudaFuncSetAttribute(xgates_mma_kernel,
                         cudaFuncAttributeMaxDynamicSharedMemorySize, XSMEM);
    cudaFuncSetAttribute(recurrent_kernel,
                         cudaFuncAttributeMaxDynamicSharedMemorySize, RSMEM);

    conv_kernel<<<23040, 256>>>(wih, input_);
    xgates_mma_kernel<<<dim3(256, 32), 128, XSMEM>>>(bih, bhh);
    init_kernel<<<256, 256>>>(h0);
    recurrent_kernel<<<GC, 256, RSMEM>>>(h0, c0, whh, retr, out);
}